// round 9
// baseline (speedup 1.0000x reference)
#include <cuda_runtime.h>

namespace {
constexpr int NX = 256, NY = 256, NZ = 128;
constexpr int NZ4 = NZ / 4, XS4 = NY * NZ4, FS4 = NX * XS4;

constexpr float CVc = 717.0f;
constexpr float MUc = 1.8e-5f, KTHc = 0.025f, Gc = 9.8f;
constexpr float Rg  = 287.0f;

constexpr double DXd = 1.0 / NX, DYd = 1.0 / NY, DZd = 1.0 / (NZ - 1);
constexpr float inv2dx = (float)(0.5 / DXd);
constexpr float inv2dy = (float)(0.5 / DYd);
constexpr float inv2dz = (float)(0.5 / DZd);
constexpr float invdx2 = (float)(1.0 / (DXd * DXd));
constexpr float invdy2 = (float)(1.0 / (DYd * DYd));
constexpr float invdz2 = (float)(1.0 / (DZd * DZd));
constexpr float kTco   = KTHc / CVc;

__device__ __forceinline__ float4 operator+(float4 a, float4 b){ return make_float4(a.x+b.x, a.y+b.y, a.z+b.z, a.w+b.w); }
__device__ __forceinline__ float4 operator-(float4 a, float4 b){ return make_float4(a.x-b.x, a.y-b.y, a.z-b.z, a.w-b.w); }
__device__ __forceinline__ float4 operator*(float4 a, float4 b){ return make_float4(a.x*b.x, a.y*b.y, a.z*b.z, a.w*b.w); }
__device__ __forceinline__ float4 operator*(float4 a, float s){ return make_float4(a.x*s, a.y*s, a.z*s, a.w*s); }
__device__ __forceinline__ float4 operator*(float s, float4 a){ return a * s; }

__device__ __forceinline__ float4 zm_of(float4 a){
    float p = __shfl_up_sync(0xffffffffu, a.w, 1);
    return make_float4(p, a.x, a.y, a.z);
}
__device__ __forceinline__ float4 zp_of(float4 a){
    float n = __shfl_down_sync(0xffffffffu, a.x, 1);
    return make_float4(a.y, a.z, a.w, n);
}
__device__ __forceinline__ float4 inv4(float4 a){
    return make_float4(1.0f/a.x, 1.0f/a.y, 1.0f/a.z, 1.0f/a.w);
}
__device__ __forceinline__ float4 maskwall(float4 v, bool lo, bool hi){
    if (lo) v.x = 0.0f;
    if (hi) v.w = 0.0f;
    return v;
}

__global__ __launch_bounds__(128, 5)
void rbx2h_kernel(const float4* __restrict__ s, float4* __restrict__ o)
{
    const int lane = threadIdx.x;                     // z chunk (4 z per lane)
    const int y  = (blockIdx.x << 2) | threadIdx.y;   // 4 y rows per block
    const int x0 = blockIdx.y << 1;                   // 2 x-points per thread

    const int bxm = ((x0 + NX - 1) & (NX - 1)) * XS4;
    const int b0  = x0 * XS4;
    const int b1  = (x0 + 1) * XS4;
    const int bxq = ((x0 + 2) & (NX - 1)) * XS4;

    const int rc_  = y * NZ4 + lane;
    const int rym_ = ((y + NY - 1) & (NY - 1)) * NZ4 + lane;
    const int ryp_ = ((y + 1)      & (NY - 1)) * NZ4 + lane;

    const bool lo = (lane == 0);
    const bool hi = (lane == 31);

    // persistent: u0,u1, vc0,vc1, wc0,wc1, rinv0,rinv1 (+ dpdx/dpdz short-lived)
    float4 u0, u1, vc0, vc1, wc0, wc1, rinv0, rinv1;
    float4 dpdx0, dpdx1, dpdz0, dpdz1;

    // ========= phase 1: rho,T,u planes + v,w centers → drou, rinv, dpdx, dpdz =========
    {
        const float4 r_xm = s[3*FS4 + bxm + rc_], r_0 = s[3*FS4 + b0 + rc_];
        const float4 r_1  = s[3*FS4 + b1  + rc_], r_xq = s[3*FS4 + bxq + rc_];
        const float4 T_xm = s[4*FS4 + bxm + rc_], T0  = s[4*FS4 + b0 + rc_];
        const float4 T1   = s[4*FS4 + b1  + rc_], T_xq = s[4*FS4 + bxq + rc_];
        const float4 u_xm = s[0*FS4 + bxm + rc_];
        u0 = s[0*FS4 + b0 + rc_];  u1 = s[0*FS4 + b1 + rc_];
        const float4 u_xq = s[0*FS4 + bxq + rc_];
        vc0 = s[1*FS4 + b0 + rc_]; vc1 = s[1*FS4 + b1 + rc_];
        wc0 = s[2*FS4 + b0 + rc_]; wc1 = s[2*FS4 + b1 + rc_];

        __stcs(&o[3*FS4 + b0 + rc_], (r_xm * u_xm - r_1 * u1) * inv2dx);
        __stcs(&o[3*FS4 + b1 + rc_], (r_0  * u0  - r_xq * u_xq) * inv2dx);

        rinv0 = inv4(r_0);
        rinv1 = inv4(r_1);

        const float4 p_xm = Rg * r_xm * T_xm;
        const float4 p0   = Rg * r_0  * T0;
        const float4 p1   = Rg * r_1  * T1;
        const float4 p_xq = Rg * r_xq * T_xq;

        dpdx0 = (p1   - p_xm) * inv2dx;
        dpdx1 = (p_xq - p0)   * inv2dx;
        dpdz0 = (zp_of(p0) - zm_of(p0)) * inv2dz;
        dpdz1 = (zp_of(p1) - zm_of(p1)) * inv2dz;
    }

    // ========= phase 2: w (consumes dpdz; (-G*rho)/rho == -G) =========
    {
        const float4 w_xm = s[2*FS4 + bxm + rc_], w_xq = s[2*FS4 + bxq + rc_];
        const float4 wym0 = s[2*FS4 + b0 + rym_], wyp0 = s[2*FS4 + b0 + ryp_];
        const float4 wym1 = s[2*FS4 + b1 + rym_], wyp1 = s[2*FS4 + b1 + ryp_];
        const float4 wzm0 = zm_of(wc0), wzp0 = zp_of(wc0);
        const float4 wzm1 = zm_of(wc1), wzp1 = zp_of(wc1);

        const float4 lapW0 = (wc1 + w_xm - wc0*2.0f)*invdx2 + (wyp0 + wym0 - wc0*2.0f)*invdy2 + (wzp0 + wzm0 - wc0*2.0f)*invdz2;
        const float4 advW0 = u0*((wc1 - w_xm)*inv2dx) + vc0*((wyp0 - wym0)*inv2dy) + wc0*((wzp0 - wzm0)*inv2dz);
        float4 dw0 = (lapW0 * MUc - dpdz0) * rinv0 - advW0;
        dw0 = make_float4(dw0.x - Gc, dw0.y - Gc, dw0.z - Gc, dw0.w - Gc);
        __stcs(&o[2*FS4 + b0 + rc_], maskwall(dw0, lo, hi));

        const float4 lapW1 = (w_xq + wc0 - wc1*2.0f)*invdx2 + (wyp1 + wym1 - wc1*2.0f)*invdy2 + (wzp1 + wzm1 - wc1*2.0f)*invdz2;
        const float4 advW1 = u1*((w_xq - wc0)*inv2dx) + vc1*((wyp1 - wym1)*inv2dy) + wc1*((wzp1 - wzm1)*inv2dz);
        float4 dw1 = (lapW1 * MUc - dpdz1) * rinv1 - advW1;
        dw1 = make_float4(dw1.x - Gc, dw1.y - Gc, dw1.z - Gc, dw1.w - Gc);
        __stcs(&o[2*FS4 + b1 + rc_], maskwall(dw1, lo, hi));
    }

    // ========= phase 3: u (consumes dpdx; u_xm/u_xq reloaded — L1 hot) =========
    {
        const float4 u_xm = s[0*FS4 + bxm + rc_], u_xq = s[0*FS4 + bxq + rc_];
        const float4 uym0 = s[0*FS4 + b0 + rym_], uyp0 = s[0*FS4 + b0 + ryp_];
        const float4 uym1 = s[0*FS4 + b1 + rym_], uyp1 = s[0*FS4 + b1 + ryp_];
        const float4 uzm0 = zm_of(u0), uzp0 = zp_of(u0);
        const float4 uzm1 = zm_of(u1), uzp1 = zp_of(u1);

        const float4 lapU0 = (u1 + u_xm - u0*2.0f)*invdx2 + (uyp0 + uym0 - u0*2.0f)*invdy2 + (uzp0 + uzm0 - u0*2.0f)*invdz2;
        const float4 advU0 = u0*((u1 - u_xm)*inv2dx) + vc0*((uyp0 - uym0)*inv2dy) + wc0*((uzp0 - uzm0)*inv2dz);
        __stcs(&o[0*FS4 + b0 + rc_], maskwall((lapU0 * MUc - dpdx0) * rinv0 - advU0, lo, hi));

        const float4 lapU1 = (u_xq + u0 - u1*2.0f)*invdx2 + (uyp1 + uym1 - u1*2.0f)*invdy2 + (uzp1 + uzm1 - u1*2.0f)*invdz2;
        const float4 advU1 = u1*((u_xq - u0)*inv2dx) + vc1*((uyp1 - uym1)*inv2dy) + wc1*((uzp1 - uzm1)*inv2dz);
        __stcs(&o[0*FS4 + b1 + rc_], maskwall((lapU1 * MUc - dpdx1) * rinv1 - advU1, lo, hi));
    }

    // ========= phase 4: v (dpdy computed here from r/T y-rows) =========
    {
        const float4 v_xm = s[1*FS4 + bxm + rc_], v_xq = s[1*FS4 + bxq + rc_];
        const float4 vym0 = s[1*FS4 + b0 + rym_], vyp0 = s[1*FS4 + b0 + ryp_];
        const float4 vym1 = s[1*FS4 + b1 + rym_], vyp1 = s[1*FS4 + b1 + ryp_];
        const float4 vzm0 = zm_of(vc0), vzp0 = zp_of(vc0);
        const float4 vzm1 = zm_of(vc1), vzp1 = zp_of(vc1);

        float4 ra = s[3*FS4 + b0 + rym_], Ta = s[4*FS4 + b0 + rym_];
        float4 rb = s[3*FS4 + b0 + ryp_], Tb = s[4*FS4 + b0 + ryp_];
        const float4 dpdy0 = (rb * Tb - ra * Ta) * (Rg * inv2dy);
        ra = s[3*FS4 + b1 + rym_]; Ta = s[4*FS4 + b1 + rym_];
        rb = s[3*FS4 + b1 + ryp_]; Tb = s[4*FS4 + b1 + ryp_];
        const float4 dpdy1 = (rb * Tb - ra * Ta) * (Rg * inv2dy);

        const float4 lapV0 = (vc1 + v_xm - vc0*2.0f)*invdx2 + (vyp0 + vym0 - vc0*2.0f)*invdy2 + (vzp0 + vzm0 - vc0*2.0f)*invdz2;
        const float4 advV0 = u0*((vc1 - v_xm)*inv2dx) + vc0*((vyp0 - vym0)*inv2dy) + wc0*((vzp0 - vzm0)*inv2dz);
        __stcs(&o[1*FS4 + b0 + rc_], maskwall((lapV0 * MUc - dpdy0) * rinv0 - advV0, lo, hi));

        const float4 lapV1 = (v_xq + vc0 - vc1*2.0f)*invdx2 + (vyp1 + vym1 - vc1*2.0f)*invdy2 + (vzp1 + vzm1 - vc1*2.0f)*invdz2;
        const float4 advV1 = u1*((v_xq - vc0)*inv2dx) + vc1*((vyp1 - vym1)*inv2dy) + wc1*((vzp1 - vzm1)*inv2dz);
        __stcs(&o[1*FS4 + b1 + rc_], maskwall((lapV1 * MUc - dpdy1) * rinv1 - advV1, lo, hi));
    }

    // ========= phase 5: dT (T reloads — L1/L2 hot) =========
    {
        const float4 T_xm = s[4*FS4 + bxm + rc_], Tc0 = s[4*FS4 + b0 + rc_];
        const float4 Tc1  = s[4*FS4 + b1  + rc_], T_xq = s[4*FS4 + bxq + rc_];
        const float4 Tym0 = s[4*FS4 + b0 + rym_], Typ0 = s[4*FS4 + b0 + ryp_];
        const float4 Tym1 = s[4*FS4 + b1 + rym_], Typ1 = s[4*FS4 + b1 + ryp_];
        const float4 Tzm0 = zm_of(Tc0), Tzp0 = zp_of(Tc0);
        const float4 Tzm1 = zm_of(Tc1), Tzp1 = zp_of(Tc1);

        const float4 lapT0 = (Tc1 + T_xm - Tc0*2.0f)*invdx2 + (Typ0 + Tym0 - Tc0*2.0f)*invdy2 + (Tzp0 + Tzm0 - Tc0*2.0f)*invdz2;
        const float4 advT0 = u0*((Tc1 - T_xm)*inv2dx) + vc0*((Typ0 - Tym0)*inv2dy) + wc0*((Tzp0 - Tzm0)*inv2dz);
        __stcs(&o[4*FS4 + b0 + rc_], maskwall((lapT0 * kTco) * rinv0 - advT0, lo, hi));

        const float4 lapT1 = (T_xq + Tc0 - Tc1*2.0f)*invdx2 + (Typ1 + Tym1 - Tc1*2.0f)*invdy2 + (Tzp1 + Tzm1 - Tc1*2.0f)*invdz2;
        const float4 advT1 = u1*((T_xq - Tc0)*inv2dx) + vc1*((Typ1 - Tym1)*inv2dy) + wc1*((Tzp1 - Tzm1)*inv2dz);
        __stcs(&o[4*FS4 + b1 + rc_], maskwall((lapT1 * kTco) * rinv1 - advT1, lo, hi));
    }

    // ========= phase 6: c (one-sided z at walls, NOT masked) =========
    {
        const float4 c_xm = s[5*FS4 + bxm + rc_], c0 = s[5*FS4 + b0 + rc_];
        const float4 c1   = s[5*FS4 + b1  + rc_], c_xq = s[5*FS4 + bxq + rc_];
        const float4 cym0 = s[5*FS4 + b0 + rym_], cyp0 = s[5*FS4 + b0 + ryp_];
        const float4 cym1 = s[5*FS4 + b1 + rym_], cyp1 = s[5*FS4 + b1 + ryp_];

        const float4 czm0 = zm_of(c0), czp0 = zp_of(c0);
        const float4 czm1 = zm_of(c1), czp1 = zp_of(c1);

        float4 dcdz0 = (czp0 - czm0) * inv2dz;
        float4 dcdz1 = (czp1 - czm1) * inv2dz;
        if (lo) {
            dcdz0.x = (-3.0f * c0.x + 4.0f * c0.y - c0.z) * inv2dz;
            dcdz1.x = (-3.0f * c1.x + 4.0f * c1.y - c1.z) * inv2dz;
        }
        if (hi) {
            dcdz0.w = ( 3.0f * c0.w - 4.0f * c0.z + c0.y) * inv2dz;
            dcdz1.w = ( 3.0f * c1.w - 4.0f * c1.z + c1.y) * inv2dz;
        }

        const float4 advC0 = u0*((c1 - c_xm)*inv2dx) + vc0*((cyp0 - cym0)*inv2dy) + wc0*dcdz0;
        __stcs(&o[5*FS4 + b0 + rc_], make_float4(-advC0.x, -advC0.y, -advC0.z, -advC0.w));
        const float4 advC1 = u1*((c_xq - c0)*inv2dx) + vc1*((cyp1 - cym1)*inv2dy) + wc1*dcdz1;
        __stcs(&o[5*FS4 + b1 + rc_], make_float4(-advC1.x, -advC1.y, -advC1.z, -advC1.w));
    }
}
} // namespace

extern "C" void kernel_launch(void* const* d_in, const int* in_sizes, int n_in,
                              void* d_out, int out_size)
{
    const float4* s = (const float4*)d_in[0];
    float4* o = (float4*)d_out;
    dim3 block(32, 4, 1);               // 128 threads: 32 z-chunks × 4 y
    dim3 grid(NY / 4, NX / 2, 1);       // 64 × 128 blocks, 2 x-points per thread
    rbx2h_kernel<<<grid, block>>>(s, o);
}